// round 9
// baseline (speedup 1.0000x reference)
#include <cuda_runtime.h>
#include <cstdint>

namespace {

constexpr int NTH  = 256;
constexpr int NCTA = 2048;   // each CTA handles 2 data blocks
constexpr int ROWS = 1024;

// cost chain: cn + cb.x*x.x + ... where x is pre-scaled by -2 (|x|^2 term dropped:
// constant across states per step, cannot change any argmin)
__device__ __forceinline__ float costf(const float4 cb, float cn, const float4 x) {
    return fmaf(cb.w, x.w, fmaf(cb.z, x.z, fmaf(cb.y, x.y, fmaf(cb.x, x.x, cn))));
}
__device__ __forceinline__ float cnrm(const float4 c) {
    return fmaf(c.w, c.w, fmaf(c.z, c.z, fmaf(c.y, c.y, c.x * c.x)));
}

// min of 4 with index embedded in the 2 LSBs of the mantissa (<=4-ulp perturbation;
// index ordering breaks forced ties toward lower j for positive values)
__device__ __forceinline__ float min4_lsb(float a0, float a1, float a2, float a3) {
    float p0 = __uint_as_float((__float_as_uint(a0) & ~3u) | 0u);
    float p1 = __uint_as_float((__float_as_uint(a1) & ~3u) | 1u);
    float p2 = __uint_as_float((__float_as_uint(a2) & ~3u) | 2u);
    float p3 = __uint_as_float((__float_as_uint(a3) & ~3u) | 3u);
    return fminf(fminf(p0, p1), fminf(p2, p3));
}

__global__ __launch_bounds__(NTH, 6)
void viterbi_kernel(const float* __restrict__ array,
                    const float* __restrict__ codebook,
                    float* __restrict__ out,
                    int out_size)
{
    __shared__ float alphaA[2][1024];
    __shared__ float alphaB[2][1024];
    __shared__ float4 xsA[64];
    __shared__ float4 xsB[64];
    __shared__ unsigned char bp[64][NTH];   // jA in bits[1:0], jB in bits[3:2]
    __shared__ int   pathA[64], pathB[64];
    __shared__ float redvA[8], redvB[8];
    __shared__ int   rediA[8], rediB[8];

    const int k  = threadIdx.x;             // state group: owns states 4k..4k+3
    const int bA = 2 * blockIdx.x;
    const int bB = bA + 1;
    const int brA = bA >> 6, bcA = bA & 63;
    const int brB = bB >> 6, bcB = bB & 63;

    // ---- load both blocks' elements, pre-scaled by -2 ----
    {
        int r = k >> 4, cc = k & 15;
        float vA = array[(brA * 16 + r) * ROWS + (bcA * 16 + cc)];
        float vB = array[(brB * 16 + r) * ROWS + (bcB * 16 + cc)];
        reinterpret_cast<float*>(xsA)[k] = -2.0f * vA;
        reinterpret_cast<float*>(xsB)[k] = -2.0f * vB;
    }

    // ---- codebook rows 4k..4k+3 in registers (shared by both chains) ----
    const float4* cb4 = reinterpret_cast<const float4*>(codebook);
    float4 o0 = __ldg(cb4 + 4 * k + 0);
    float4 o1 = __ldg(cb4 + 4 * k + 1);
    float4 o2 = __ldg(cb4 + 4 * k + 2);
    float4 o3 = __ldg(cb4 + 4 * k + 3);
    float cn0 = cnrm(o0), cn1 = cnrm(o1), cn2 = cnrm(o2), cn3 = cnrm(o3);

    __syncthreads();

    // ---- alpha_0 = cost(x0) for both blocks ----
    float vA0, vA1, vA2, vA3, vB0, vB1, vB2, vB3;
    {
        float4 xA = xsA[0], xB = xsB[0];
        vA0 = costf(o0, cn0, xA); vA1 = costf(o1, cn1, xA);
        vA2 = costf(o2, cn2, xA); vA3 = costf(o3, cn3, xA);
        vB0 = costf(o0, cn0, xB); vB1 = costf(o1, cn1, xB);
        vB2 = costf(o2, cn2, xB); vB3 = costf(o3, cn3, xB);
        *reinterpret_cast<float4*>(&alphaA[0][4 * k]) = make_float4(vA0, vA1, vA2, vA3);
        *reinterpret_cast<float4*>(&alphaB[0][4 * k]) = make_float4(vB0, vB1, vB2, vB3);
    }
    __syncthreads();

    // ---- forward recursion: 63 steps, two independent chains interleaved ----
#pragma unroll 2
    for (int t = 1; t < 64; ++t) {
        const float* apA = alphaA[(t + 1) & 1];
        const float* apB = alphaB[(t + 1) & 1];
        float aA0 = apA[k], aA1 = apA[k + 256], aA2 = apA[k + 512], aA3 = apA[k + 768];
        float aB0 = apB[k], aB1 = apB[k + 256], aB2 = apB[k + 512], aB3 = apB[k + 768];

        // LSB-embedded argmin (index in mantissa LSBs)
        float mA = min4_lsb(aA0, aA1, aA2, aA3);
        float mB = min4_lsb(aB0, aB1, aB2, aB3);
        unsigned jA = __float_as_uint(mA) & 3u;
        unsigned jB = __float_as_uint(mB) & 3u;
        bp[t][k] = (unsigned char)(jA | (jB << 2));

        float4 xA = xsA[t], xB = xsB[t];
        vA0 = mA + costf(o0, cn0, xA); vA1 = mA + costf(o1, cn1, xA);
        vA2 = mA + costf(o2, cn2, xA); vA3 = mA + costf(o3, cn3, xA);
        vB0 = mB + costf(o0, cn0, xB); vB1 = mB + costf(o1, cn1, xB);
        vB2 = mB + costf(o2, cn2, xB); vB3 = mB + costf(o3, cn3, xB);
        *reinterpret_cast<float4*>(&alphaA[t & 1][4 * k]) = make_float4(vA0, vA1, vA2, vA3);
        *reinterpret_cast<float4*>(&alphaB[t & 1][4 * k]) = make_float4(vB0, vB1, vB2, vB3);
        __syncthreads();
    }

    // ---- final argmin over 1024 states for both blocks (first-occurrence) ----
    {
        float bm = vA0; int bi = 4 * k;
        if (vA1 < bm) { bm = vA1; bi = 4 * k + 1; }
        if (vA2 < bm) { bm = vA2; bi = 4 * k + 2; }
        if (vA3 < bm) { bm = vA3; bi = 4 * k + 3; }
        float cm = vB0; int ci = 4 * k;
        if (vB1 < cm) { cm = vB1; ci = 4 * k + 1; }
        if (vB2 < cm) { cm = vB2; ci = 4 * k + 2; }
        if (vB3 < cm) { cm = vB3; ci = 4 * k + 3; }
#pragma unroll
        for (int off = 16; off; off >>= 1) {
            float om = __shfl_down_sync(0xffffffffu, bm, off);
            int   oi = __shfl_down_sync(0xffffffffu, bi, off);
            if (om < bm || (om == bm && oi < bi)) { bm = om; bi = oi; }
            float pm = __shfl_down_sync(0xffffffffu, cm, off);
            int   pi = __shfl_down_sync(0xffffffffu, ci, off);
            if (pm < cm || (pm == cm && pi < ci)) { cm = pm; ci = pi; }
        }
        if ((k & 31) == 0) {
            redvA[k >> 5] = bm; rediA[k >> 5] = bi;
            redvB[k >> 5] = cm; rediB[k >> 5] = ci;
        }
    }
    __syncthreads();

    // ---- backtrack: thread 0 does A, thread 32 does B (parallel warps) ----
    if (k == 0) {
        float m = redvA[0]; int s = rediA[0];
#pragma unroll
        for (int w = 1; w < 8; ++w)
            if (redvA[w] < m || (redvA[w] == m && rediA[w] < s)) { m = redvA[w]; s = rediA[w]; }
        pathA[63] = s;
        for (int t = 63; t >= 1; --t) {
            int g = s >> 2;
            int j = bp[t][g] & 3;
            s = g + (j << 8);                // prev = (s>>2) + j*HI, HI = 256
            pathA[t - 1] = s;
        }
    }
    if (k == 32) {
        float m = redvB[0]; int s = rediB[0];
#pragma unroll
        for (int w = 1; w < 8; ++w)
            if (redvB[w] < m || (redvB[w] == m && rediB[w] < s)) { m = redvB[w]; s = rediB[w]; }
        pathB[63] = s;
        for (int t = 63; t >= 1; --t) {
            int g = s >> 2;
            int j = (bp[t][g] >> 2) & 3;
            s = g + (j << 8);
            pathB[t - 1] = s;
        }
    }
    __syncthreads();

    // ---- emit: rec (exact codebook gather) + states, both blocks ----
    if (k < 128) {
        int t = k & 63;
        bool isB = k >= 64;
        int s = isB ? pathB[t] : pathA[t];
        int bb = isB ? bB : bA;
        int br = isB ? brB : brA;
        int bc = isB ? bcB : bcA;
        float4 val = __ldg(cb4 + s);
        int row = br * 16 + (t >> 2);
        int col = bc * 16 + ((t & 3) << 2);
        reinterpret_cast<float4*>(out + row * ROWS + col)[0] = val;
        int sidx = ROWS * ROWS + bb * 64 + t;
        if (sidx < out_size) out[sidx] = (float)s;
    }
}

} // namespace

extern "C" void kernel_launch(void* const* d_in, const int* in_sizes, int n_in,
                              void* d_out, int out_size) {
    const float* array    = (const float*)d_in[0];
    const float* codebook = (const float*)d_in[1];
    (void)in_sizes; (void)n_in;
    float* out = (float*)d_out;
    viterbi_kernel<<<NCTA, NTH>>>(array, codebook, out, out_size);
}

// round 10
// speedup vs baseline: 1.0778x; 1.0778x over previous
#include <cuda_runtime.h>
#include <cstdint>

namespace {

constexpr int NTH  = 256;
constexpr int NCTA = 2048;   // each CTA handles 2 data blocks
constexpr int ROWS = 1024;

// cost chain: cn + cb.x*x.x + ... where x is pre-scaled by -2 (|x|^2 term dropped:
// constant across states per step, cannot change any argmin)
__device__ __forceinline__ float costf(const float4 cb, float cn, const float4 x) {
    return fmaf(cb.w, x.w, fmaf(cb.z, x.z, fmaf(cb.y, x.y, fmaf(cb.x, x.x, cn))));
}
__device__ __forceinline__ float cnrm(const float4 c) {
    return fmaf(c.w, c.w, fmaf(c.z, c.z, fmaf(c.y, c.y, c.x * c.x)));
}

__global__ __launch_bounds__(NTH, 5)
void viterbi_kernel(const float* __restrict__ array,
                    const float* __restrict__ codebook,
                    float* __restrict__ out,
                    int out_size)
{
    __shared__ float alphaA[2][1024];
    __shared__ float alphaB[2][1024];
    __shared__ float4 xsA[64];
    __shared__ float4 xsB[64];
    __shared__ unsigned char bp[64][NTH];   // jA in bits[1:0], jB in bits[3:2]
    __shared__ int   pathA[64], pathB[64];
    __shared__ float redvA[8], redvB[8];
    __shared__ int   rediA[8], rediB[8];

    const int k  = threadIdx.x;             // state group: owns states 4k..4k+3
    const int bA = 2 * blockIdx.x;
    const int bB = bA + 1;
    const int brA = bA >> 6, bcA = bA & 63;
    const int brB = bB >> 6, bcB = bB & 63;

    // ---- load both blocks' elements, pre-scaled by -2 ----
    {
        int r = k >> 4, cc = k & 15;
        float vA = array[(brA * 16 + r) * ROWS + (bcA * 16 + cc)];
        float vB = array[(brB * 16 + r) * ROWS + (bcB * 16 + cc)];
        reinterpret_cast<float*>(xsA)[k] = -2.0f * vA;
        reinterpret_cast<float*>(xsB)[k] = -2.0f * vB;
    }

    // ---- codebook rows 4k..4k+3 in registers (shared by both chains) ----
    const float4* cb4 = reinterpret_cast<const float4*>(codebook);
    float4 o0 = __ldg(cb4 + 4 * k + 0);
    float4 o1 = __ldg(cb4 + 4 * k + 1);
    float4 o2 = __ldg(cb4 + 4 * k + 2);
    float4 o3 = __ldg(cb4 + 4 * k + 3);
    float cn0 = cnrm(o0), cn1 = cnrm(o1), cn2 = cnrm(o2), cn3 = cnrm(o3);

    __syncthreads();

    // ---- alpha_0 = cost(x0) for both blocks ----
    float vA0, vA1, vA2, vA3, vB0, vB1, vB2, vB3;
    {
        float4 xA = xsA[0], xB = xsB[0];
        vA0 = costf(o0, cn0, xA); vA1 = costf(o1, cn1, xA);
        vA2 = costf(o2, cn2, xA); vA3 = costf(o3, cn3, xA);
        vB0 = costf(o0, cn0, xB); vB1 = costf(o1, cn1, xB);
        vB2 = costf(o2, cn2, xB); vB3 = costf(o3, cn3, xB);
        *reinterpret_cast<float4*>(&alphaA[0][4 * k]) = make_float4(vA0, vA1, vA2, vA3);
        *reinterpret_cast<float4*>(&alphaB[0][4 * k]) = make_float4(vB0, vB1, vB2, vB3);
    }
    __syncthreads();

    // ---- forward recursion: 63 steps, two independent chains interleaved ----
    // Scheduling: alpha LDS issued first; the 32 independent cost FMAs (dep only
    // on xs[t], loaded at CTA start) cover the LDS latency inside each thread.
#pragma unroll 4
    for (int t = 1; t < 64; ++t) {
        const float* apA = alphaA[(t + 1) & 1];
        const float* apB = alphaB[(t + 1) & 1];
        // 1) issue the long-latency loads first
        float aA0 = apA[k], aA1 = apA[k + 256], aA2 = apA[k + 512], aA3 = apA[k + 768];
        float aB0 = apB[k], aB1 = apB[k + 256], aB2 = apB[k + 512], aB3 = apB[k + 768];

        // 2) barrier-independent cost chains (fill the load-use gap)
        float4 xA = xsA[t], xB = xsB[t];
        float cA0 = costf(o0, cn0, xA), cA1 = costf(o1, cn1, xA);
        float cA2 = costf(o2, cn2, xA), cA3 = costf(o3, cn3, xA);
        float cB0 = costf(o0, cn0, xB), cB1 = costf(o1, cn1, xB);
        float cB2 = costf(o2, cn2, xB), cB3 = costf(o3, cn3, xB);

        // 3) consume loads: strict-< first-occurrence argmin
        float mA = aA0; int jA = 0;
        if (aA1 < mA) { mA = aA1; jA = 1; }
        if (aA2 < mA) { mA = aA2; jA = 2; }
        if (aA3 < mA) { mA = aA3; jA = 3; }
        float mB = aB0; int jB = 0;
        if (aB1 < mB) { mB = aB1; jB = 1; }
        if (aB2 < mB) { mB = aB2; jB = 2; }
        if (aB3 < mB) { mB = aB3; jB = 3; }
        bp[t][k] = (unsigned char)(jA | (jB << 2));

        // 4) combine + store
        vA0 = mA + cA0; vA1 = mA + cA1; vA2 = mA + cA2; vA3 = mA + cA3;
        vB0 = mB + cB0; vB1 = mB + cB1; vB2 = mB + cB2; vB3 = mB + cB3;
        *reinterpret_cast<float4*>(&alphaA[t & 1][4 * k]) = make_float4(vA0, vA1, vA2, vA3);
        *reinterpret_cast<float4*>(&alphaB[t & 1][4 * k]) = make_float4(vB0, vB1, vB2, vB3);
        __syncthreads();
    }

    // ---- final argmin over 1024 states for both blocks (first-occurrence) ----
    {
        float bm = vA0; int bi = 4 * k;
        if (vA1 < bm) { bm = vA1; bi = 4 * k + 1; }
        if (vA2 < bm) { bm = vA2; bi = 4 * k + 2; }
        if (vA3 < bm) { bm = vA3; bi = 4 * k + 3; }
        float cm = vB0; int ci = 4 * k;
        if (vB1 < cm) { cm = vB1; ci = 4 * k + 1; }
        if (vB2 < cm) { cm = vB2; ci = 4 * k + 2; }
        if (vB3 < cm) { cm = vB3; ci = 4 * k + 3; }
#pragma unroll
        for (int off = 16; off; off >>= 1) {
            float om = __shfl_down_sync(0xffffffffu, bm, off);
            int   oi = __shfl_down_sync(0xffffffffu, bi, off);
            if (om < bm || (om == bm && oi < bi)) { bm = om; bi = oi; }
            float pm = __shfl_down_sync(0xffffffffu, cm, off);
            int   pi = __shfl_down_sync(0xffffffffu, ci, off);
            if (pm < cm || (pm == cm && pi < ci)) { cm = pm; ci = pi; }
        }
        if ((k & 31) == 0) {
            redvA[k >> 5] = bm; rediA[k >> 5] = bi;
            redvB[k >> 5] = cm; rediB[k >> 5] = ci;
        }
    }
    __syncthreads();

    // ---- backtrack: thread 0 does A, thread 32 does B (parallel warps) ----
    if (k == 0) {
        float m = redvA[0]; int s = rediA[0];
#pragma unroll
        for (int w = 1; w < 8; ++w)
            if (redvA[w] < m || (redvA[w] == m && rediA[w] < s)) { m = redvA[w]; s = rediA[w]; }
        pathA[63] = s;
        for (int t = 63; t >= 1; --t) {
            int g = s >> 2;
            int j = bp[t][g] & 3;
            s = g + (j << 8);                // prev = (s>>2) + j*HI, HI = 256
            pathA[t - 1] = s;
        }
    }
    if (k == 32) {
        float m = redvB[0]; int s = rediB[0];
#pragma unroll
        for (int w = 1; w < 8; ++w)
            if (redvB[w] < m || (redvB[w] == m && rediB[w] < s)) { m = redvB[w]; s = rediB[w]; }
        pathB[63] = s;
        for (int t = 63; t >= 1; --t) {
            int g = s >> 2;
            int j = (bp[t][g] >> 2) & 3;
            s = g + (j << 8);
            pathB[t - 1] = s;
        }
    }
    __syncthreads();

    // ---- emit: rec (exact codebook gather) + states, both blocks ----
    if (k < 128) {
        int t = k & 63;
        bool isB = k >= 64;
        int s = isB ? pathB[t] : pathA[t];
        int bb = isB ? bB : bA;
        int br = isB ? brB : brA;
        int bc = isB ? bcB : bcA;
        float4 val = __ldg(cb4 + s);
        int row = br * 16 + (t >> 2);
        int col = bc * 16 + ((t & 3) << 2);
        reinterpret_cast<float4*>(out + row * ROWS + col)[0] = val;
        int sidx = ROWS * ROWS + bb * 64 + t;
        if (sidx < out_size) out[sidx] = (float)s;
    }
}

} // namespace

extern "C" void kernel_launch(void* const* d_in, const int* in_sizes, int n_in,
                              void* d_out, int out_size) {
    const float* array    = (const float*)d_in[0];
    const float* codebook = (const float*)d_in[1];
    (void)in_sizes; (void)n_in;
    float* out = (float*)d_out;
    viterbi_kernel<<<NCTA, NTH>>>(array, codebook, out, out_size);
}